// round 1
// baseline (speedup 1.0000x reference)
#include <cuda_runtime.h>
#include <cstdint>

#define EPSF 1e-6f
#define L2E  1.44269504088896340736f

constexpr int SI = 3000;
constexpr int SJ = 3000;
constexpr int NLINKS = 500000;
constexpr int BT = 256;          // threads per block
constexpr int LINK_BLOCKS = 512;

// ---------------- scratch (no allocations allowed) ----------------
__device__ float g_ziE[SI * 8];       // gathered zi rows, EPS pre-added
__device__ float g_bL[SI];            // beta[sample_i] * log2(e)
__device__ float g_zj[SJ * 8];        // gathered zj rows
__device__ float g_gL[SJ];            // gamma[sample_j] * log2(e)
__device__ float g_part_block[SI];    // one partial per i-block
__device__ float g_part_links[LINK_BLOCKS];

// ---------------- gather + prescale ----------------
__global__ void gather_kernel(const float* __restrict__ zi,
                              const float* __restrict__ zj,
                              const float* __restrict__ beta,
                              const float* __restrict__ gamma,
                              const int*   __restrict__ si,
                              const int*   __restrict__ sj) {
    int t = blockIdx.x * blockDim.x + threadIdx.x;
    if (t < SI) {
        int i = si[t];
        #pragma unroll
        for (int k = 0; k < 8; k++) g_ziE[t * 8 + k] = zi[i * 8 + k] + EPSF;
        g_bL[t] = beta[i] * L2E;
    }
    if (t < SJ) {
        int j = sj[t];
        #pragma unroll
        for (int k = 0; k < 8; k++) g_zj[t * 8 + k] = zj[j * 8 + k];
        g_gL[t] = gamma[j] * L2E;
    }
}

// ---------------- sampled-block term: sum exp(beta_i+gamma_j-dist) ----------------
// One block per sampled i; threads stride over j. All tables L1-resident.
__global__ __launch_bounds__(BT) void block_kernel() {
    const int i = blockIdx.x;
    const float4 a0 = *(const float4*)&g_ziE[i * 8];
    const float4 a1 = *(const float4*)&g_ziE[i * 8 + 4];
    const float  bL = g_bL[i];

    float acc = 0.0f;
    #pragma unroll 4
    for (int j = threadIdx.x; j < SJ; j += BT) {
        const float4 b0 = *(const float4*)&g_zj[j * 8];
        const float4 b1 = *(const float4*)&g_zj[j * 8 + 4];
        float d0 = a0.x - b0.x, d1 = a0.y - b0.y, d2 = a0.z - b0.z, d3 = a0.w - b0.w;
        float d4 = a1.x - b1.x, d5 = a1.y - b1.y, d6 = a1.z - b1.z, d7 = a1.w - b1.w;
        float s = d0 * d0;
        s = fmaf(d1, d1, s); s = fmaf(d2, d2, s); s = fmaf(d3, d3, s);
        s = fmaf(d4, d4, s); s = fmaf(d5, d5, s); s = fmaf(d6, d6, s);
        s = fmaf(d7, d7, s);
        s = fmaxf(s, 1e-35f);
        float u = rsqrtf(s);              // MUFU.RSQ
        float dist = s * u;               // sqrt(s)
        float t = fmaf(dist, -L2E, bL + g_gL[j]);
        float e;
        asm("ex2.approx.f32 %0, %1;" : "=f"(e) : "f"(t));  // MUFU.EX2
        acc += e;
    }

    __shared__ float red[BT];
    red[threadIdx.x] = acc;
    __syncthreads();
    #pragma unroll
    for (int s2 = BT / 2; s2 > 0; s2 >>= 1) {
        if (threadIdx.x < s2) red[threadIdx.x] += red[threadIdx.x + s2];
        __syncthreads();
    }
    if (threadIdx.x == 0) g_part_block[i] = red[0];
}

// ---------------- link term: sum (beta_i + gamma_j - dist) over edges ----------------
__global__ __launch_bounds__(BT) void links_kernel(const float* __restrict__ zi,
                                                   const float* __restrict__ zj,
                                                   const float* __restrict__ beta,
                                                   const float* __restrict__ gamma,
                                                   const int*   __restrict__ li,
                                                   const int*   __restrict__ lj) {
    const int stride = gridDim.x * blockDim.x;
    float acc = 0.0f;
    for (int e = blockIdx.x * blockDim.x + threadIdx.x; e < NLINKS; e += stride) {
        const int i = li[e];
        const int j = lj[e];
        const float4 a0 = *(const float4*)&zi[i * 8];
        const float4 a1 = *(const float4*)&zi[i * 8 + 4];
        const float4 b0 = *(const float4*)&zj[j * 8];
        const float4 b1 = *(const float4*)&zj[j * 8 + 4];
        float d0 = a0.x - b0.x + EPSF, d1 = a0.y - b0.y + EPSF;
        float d2 = a0.z - b0.z + EPSF, d3 = a0.w - b0.w + EPSF;
        float d4 = a1.x - b1.x + EPSF, d5 = a1.y - b1.y + EPSF;
        float d6 = a1.z - b1.z + EPSF, d7 = a1.w - b1.w + EPSF;
        float s = d0 * d0;
        s = fmaf(d1, d1, s); s = fmaf(d2, d2, s); s = fmaf(d3, d3, s);
        s = fmaf(d4, d4, s); s = fmaf(d5, d5, s); s = fmaf(d6, d6, s);
        s = fmaf(d7, d7, s);
        s = fmaxf(s, 1e-35f);
        float u = rsqrtf(s);
        float dist = s * u;
        acc += beta[i] + gamma[j] - dist;
    }

    __shared__ float red[BT];
    red[threadIdx.x] = acc;
    __syncthreads();
    #pragma unroll
    for (int s2 = BT / 2; s2 > 0; s2 >>= 1) {
        if (threadIdx.x < s2) red[threadIdx.x] += red[threadIdx.x + s2];
        __syncthreads();
    }
    if (threadIdx.x == 0) g_part_links[blockIdx.x] = red[0];
}

// ---------------- final deterministic reduction (double precision) ----------------
__global__ __launch_bounds__(BT) void final_kernel(float* __restrict__ out) {
    __shared__ double redB[BT];
    __shared__ double redL[BT];
    double sb = 0.0, sl = 0.0;
    for (int k = threadIdx.x; k < SI; k += BT)          sb += (double)g_part_block[k];
    for (int k = threadIdx.x; k < LINK_BLOCKS; k += BT) sl += (double)g_part_links[k];
    redB[threadIdx.x] = sb;
    redL[threadIdx.x] = sl;
    __syncthreads();
    #pragma unroll
    for (int s2 = BT / 2; s2 > 0; s2 >>= 1) {
        if (threadIdx.x < s2) {
            redB[threadIdx.x] += redB[threadIdx.x + s2];
            redL[threadIdx.x] += redL[threadIdx.x + s2];
        }
        __syncthreads();
    }
    if (threadIdx.x == 0) out[0] = (float)(redL[0] - redB[0]);
}

extern "C" void kernel_launch(void* const* d_in, const int* in_sizes, int n_in,
                              void* d_out, int out_size) {
    const float* latent_zi = (const float*)d_in[0];
    const float* latent_zj = (const float*)d_in[1];
    const float* beta      = (const float*)d_in[2];
    const float* gamma     = (const float*)d_in[3];
    const int*   si        = (const int*)  d_in[4];
    const int*   sj        = (const int*)  d_in[5];
    const int*   li        = (const int*)  d_in[6];
    const int*   lj        = (const int*)  d_in[7];
    float* out = (float*)d_out;

    gather_kernel<<<(SI + BT - 1) / BT, BT>>>(latent_zi, latent_zj, beta, gamma, si, sj);
    block_kernel<<<SI, BT>>>();
    links_kernel<<<LINK_BLOCKS, BT>>>(latent_zi, latent_zj, beta, gamma, li, lj);
    final_kernel<<<1, BT>>>(out);
}

// round 2
// speedup vs baseline: 1.3469x; 1.3469x over previous
#include <cuda_runtime.h>
#include <cstdint>

#define EPSF 1e-6f
#define L2E  1.44269504088896340736f

constexpr int SI = 3000;
constexpr int SJ = 3000;
constexpr int NLINKS = 500000;
constexpr int BT = 256;
constexpr int GATHER_BLOCKS = (SI + BT - 1) / BT;   // 12
constexpr int LINK_BLOCKS = 296;
constexpr int IT = 4;                               // i's per block in block term
constexpr int NBI = SI / IT;                        // 750 blocks

// ---------------- scratch ----------------
__device__ float4 g_zi0[SI], g_zi1[SI];      // gathered zi rows, EPS pre-added
__device__ float  g_bL[SI];                  // beta[si]*log2(e)
__device__ float4 g_zj0[SJ], g_zj1[SJ];      // gathered zj rows
__device__ float  g_gL[SJ];                  // gamma[sj]*log2(e)
__device__ float  g_part_block[NBI];
__device__ float  g_part_links[LINK_BLOCKS];
__device__ int    g_ticket;

__device__ __forceinline__ float warp_sum(float v) {
    #pragma unroll
    for (int o = 16; o > 0; o >>= 1) v += __shfl_xor_sync(0xffffffffu, v, o);
    return v;
}

// block-level sum of per-thread value; result valid in thread 0
__device__ __forceinline__ float block_sum(float v) {
    __shared__ float w[BT / 32];
    v = warp_sum(v);
    if ((threadIdx.x & 31) == 0) w[threadIdx.x >> 5] = v;
    __syncthreads();
    if (threadIdx.x < BT / 32) {
        v = w[threadIdx.x];
        #pragma unroll
        for (int o = BT / 64; o > 0; o >>= 1) v += __shfl_xor_sync(0xffu, v, o);
    }
    return v;
}

// ================= kernel 1: gather + link term =================
__global__ __launch_bounds__(BT) void k1(const float* __restrict__ zi,
                                         const float* __restrict__ zj,
                                         const float* __restrict__ beta,
                                         const float* __restrict__ gamma,
                                         const int*   __restrict__ si,
                                         const int*   __restrict__ sj,
                                         const int*   __restrict__ li,
                                         const int*   __restrict__ lj) {
    if (blockIdx.x < GATHER_BLOCKS) {
        int t = blockIdx.x * BT + threadIdx.x;
        if (t == 0) g_ticket = 0;
        if (t < SI) {
            int i = si[t];
            float4 a0 = __ldg((const float4*)&zi[i * 8]);
            float4 a1 = __ldg((const float4*)&zi[i * 8 + 4]);
            a0.x += EPSF; a0.y += EPSF; a0.z += EPSF; a0.w += EPSF;
            a1.x += EPSF; a1.y += EPSF; a1.z += EPSF; a1.w += EPSF;
            g_zi0[t] = a0; g_zi1[t] = a1;
            g_bL[t] = beta[i] * L2E;
        }
        if (t < SJ) {
            int j = sj[t];
            g_zj0[t] = __ldg((const float4*)&zj[j * 8]);
            g_zj1[t] = __ldg((const float4*)&zj[j * 8 + 4]);
            g_gL[t] = gamma[j] * L2E;
        }
        return;
    }

    // ---- link term ----
    const int b = blockIdx.x - GATHER_BLOCKS;
    const int stride = LINK_BLOCKS * BT;
    float acc = 0.0f;
    for (int e = b * BT + threadIdx.x; e < NLINKS; e += stride) {
        const int i = li[e];
        const int j = lj[e];
        const float4 a0 = __ldg((const float4*)&zi[i * 8]);
        const float4 a1 = __ldg((const float4*)&zi[i * 8 + 4]);
        const float4 b0 = __ldg((const float4*)&zj[j * 8]);
        const float4 b1 = __ldg((const float4*)&zj[j * 8 + 4]);
        float d0 = a0.x - b0.x + EPSF, d1 = a0.y - b0.y + EPSF;
        float d2 = a0.z - b0.z + EPSF, d3 = a0.w - b0.w + EPSF;
        float d4 = a1.x - b1.x + EPSF, d5 = a1.y - b1.y + EPSF;
        float d6 = a1.z - b1.z + EPSF, d7 = a1.w - b1.w + EPSF;
        float s = d0 * d0;
        s = fmaf(d1, d1, s); s = fmaf(d2, d2, s); s = fmaf(d3, d3, s);
        s = fmaf(d4, d4, s); s = fmaf(d5, d5, s); s = fmaf(d6, d6, s);
        s = fmaf(d7, d7, s);
        s = fmaxf(s, 1e-35f);
        float u = rsqrtf(s);
        acc += __ldg(&beta[i]) + __ldg(&gamma[j]) - s * u;
    }
    float tot = block_sum(acc);
    if (threadIdx.x == 0) g_part_links[b] = tot;
}

// ================= kernel 2: sampled block term + final reduce =================
__global__ __launch_bounds__(BT) void k2(float* __restrict__ out) {
    const int ib = blockIdx.x * IT;

    float4 a0[IT], a1[IT];
    float  bL[IT];
    #pragma unroll
    for (int u = 0; u < IT; u++) {
        a0[u] = g_zi0[ib + u];
        a1[u] = g_zi1[ib + u];
        bL[u] = g_bL[ib + u];
    }

    float acc = 0.0f;
    for (int j = threadIdx.x; j < SJ; j += BT) {
        const float4 b0 = g_zj0[j];
        const float4 b1 = g_zj1[j];
        const float  gL = g_gL[j];
        #pragma unroll
        for (int u = 0; u < IT; u++) {
            float d0 = a0[u].x - b0.x, d1 = a0[u].y - b0.y;
            float d2 = a0[u].z - b0.z, d3 = a0[u].w - b0.w;
            float d4 = a1[u].x - b1.x, d5 = a1[u].y - b1.y;
            float d6 = a1[u].z - b1.z, d7 = a1[u].w - b1.w;
            float s = d0 * d0;
            s = fmaf(d1, d1, s); s = fmaf(d2, d2, s); s = fmaf(d3, d3, s);
            s = fmaf(d4, d4, s); s = fmaf(d5, d5, s); s = fmaf(d6, d6, s);
            s = fmaf(d7, d7, s);
            s = fmaxf(s, 1e-35f);
            float r = rsqrtf(s);                      // MUFU.RSQ
            float t = fmaf(s * r, -L2E, bL[u] + gL);  // log2-domain exponent
            float e;
            asm("ex2.approx.f32 %0, %1;" : "=f"(e) : "f"(t));  // MUFU.EX2
            acc += e;
        }
    }

    float tot = block_sum(acc);
    if (threadIdx.x == 0) g_part_block[blockIdx.x] = tot;

    // ---- last-arriving block performs the deterministic final reduction ----
    __shared__ int isLast;
    __threadfence();
    if (threadIdx.x == 0) isLast = (atomicAdd(&g_ticket, 1) == NBI - 1);
    __syncthreads();
    if (!isLast) return;

    __shared__ double redB[BT], redL[BT];
    double sb = 0.0, sl = 0.0;
    for (int k = threadIdx.x; k < NBI; k += BT)         sb += (double)g_part_block[k];
    for (int k = threadIdx.x; k < LINK_BLOCKS; k += BT) sl += (double)g_part_links[k];
    redB[threadIdx.x] = sb;
    redL[threadIdx.x] = sl;
    __syncthreads();
    #pragma unroll
    for (int s2 = BT / 2; s2 > 0; s2 >>= 1) {
        if (threadIdx.x < s2) {
            redB[threadIdx.x] += redB[threadIdx.x + s2];
            redL[threadIdx.x] += redL[threadIdx.x + s2];
        }
        __syncthreads();
    }
    if (threadIdx.x == 0) out[0] = (float)(redL[0] - redB[0]);
}

extern "C" void kernel_launch(void* const* d_in, const int* in_sizes, int n_in,
                              void* d_out, int out_size) {
    const float* latent_zi = (const float*)d_in[0];
    const float* latent_zj = (const float*)d_in[1];
    const float* beta      = (const float*)d_in[2];
    const float* gamma     = (const float*)d_in[3];
    const int*   si        = (const int*)  d_in[4];
    const int*   sj        = (const int*)  d_in[5];
    const int*   li        = (const int*)  d_in[6];
    const int*   lj        = (const int*)  d_in[7];
    float* out = (float*)d_out;

    k1<<<GATHER_BLOCKS + LINK_BLOCKS, BT>>>(latent_zi, latent_zj, beta, gamma, si, sj, li, lj);
    k2<<<NBI, BT>>>(out);
}

// round 3
// speedup vs baseline: 1.5847x; 1.1765x over previous
#include <cuda_runtime.h>
#include <cstdint>

#define EPSF 1e-6f
#define L2E  1.44269504088896340736f

constexpr int SI = 3000;
constexpr int SJ = 3000;
constexpr int NLINKS = 500000;
constexpr int BT = 256;
constexpr int GATHER_BLOCKS = (SI + BT - 1) / BT;   // 12
constexpr int IT = 4;                               // i's per block-term block
constexpr int NBI = SI / IT;                        // 750
constexpr int K2_LINK = 296;                        // link blocks (first in grid)
constexpr int K2_TOTAL = K2_LINK + NBI;

// ---------------- scratch ----------------
__device__ float4 g_zi0[SI], g_zi1[SI];      // gathered zi rows, EPS pre-added
__device__ float  g_bL[SI];                  // beta[si]*log2(e)
__device__ float4 g_zj0[SJ], g_zj1[SJ];      // gathered zj rows, NEGATED
__device__ float  g_gL[SJ];                  // gamma[sj]*log2(e)
__device__ float  g_part_block[NBI];
__device__ float  g_part_links[K2_LINK];
__device__ int    g_ticket;

typedef unsigned long long u64;

__device__ __forceinline__ u64 ADD2(u64 a, u64 b) {
    u64 r; asm("add.rn.f32x2 %0,%1,%2;" : "=l"(r) : "l"(a), "l"(b)); return r;
}
__device__ __forceinline__ u64 MUL2(u64 a, u64 b) {
    u64 r; asm("mul.rn.f32x2 %0,%1,%2;" : "=l"(r) : "l"(a), "l"(b)); return r;
}
__device__ __forceinline__ u64 FMA2(u64 a, u64 b, u64 c) {
    u64 r; asm("fma.rn.f32x2 %0,%1,%2,%3;" : "=l"(r) : "l"(a), "l"(b), "l"(c)); return r;
}
__device__ __forceinline__ float LOHI_ADD(u64 v) {
    unsigned lo, hi;
    asm("mov.b64 {%0,%1}, %2;" : "=r"(lo), "=r"(hi) : "l"(v));
    return __uint_as_float(lo) + __uint_as_float(hi);
}

__device__ __forceinline__ float warp_sum(float v) {
    #pragma unroll
    for (int o = 16; o > 0; o >>= 1) v += __shfl_xor_sync(0xffffffffu, v, o);
    return v;
}
__device__ __forceinline__ float block_sum(float v) {
    __shared__ float w[BT / 32];
    v = warp_sum(v);
    if ((threadIdx.x & 31) == 0) w[threadIdx.x >> 5] = v;
    __syncthreads();
    if (threadIdx.x < BT / 32) {
        v = w[threadIdx.x];
        #pragma unroll
        for (int o = BT / 64; o > 0; o >>= 1) v += __shfl_xor_sync(0xffu, v, o);
    }
    return v;
}

// ================= kernel 1: gather only (tiny) =================
__global__ __launch_bounds__(BT) void k1(const float* __restrict__ zi,
                                         const float* __restrict__ zj,
                                         const float* __restrict__ beta,
                                         const float* __restrict__ gamma,
                                         const int*   __restrict__ si,
                                         const int*   __restrict__ sj) {
    int t = blockIdx.x * BT + threadIdx.x;
    if (t == 0) g_ticket = 0;
    if (t < SI) {
        int i = si[t];
        float4 a0 = __ldg((const float4*)&zi[i * 8]);
        float4 a1 = __ldg((const float4*)&zi[i * 8 + 4]);
        a0.x += EPSF; a0.y += EPSF; a0.z += EPSF; a0.w += EPSF;
        a1.x += EPSF; a1.y += EPSF; a1.z += EPSF; a1.w += EPSF;
        g_zi0[t] = a0; g_zi1[t] = a1;
        g_bL[t] = beta[i] * L2E;
    }
    if (t < SJ) {
        int j = sj[t];
        float4 b0 = __ldg((const float4*)&zj[j * 8]);
        float4 b1 = __ldg((const float4*)&zj[j * 8 + 4]);
        b0.x = -b0.x; b0.y = -b0.y; b0.z = -b0.z; b0.w = -b0.w;
        b1.x = -b1.x; b1.y = -b1.y; b1.z = -b1.z; b1.w = -b1.w;
        g_zj0[t] = b0; g_zj1[t] = b1;
        g_gL[t] = gamma[j] * L2E;
    }
}

// ================= kernel 2: links + block term + final reduce =================
__global__ __launch_bounds__(BT) void k2(const float* __restrict__ zi,
                                         const float* __restrict__ zj,
                                         const float* __restrict__ beta,
                                         const float* __restrict__ gamma,
                                         const int*   __restrict__ li,
                                         const int*   __restrict__ lj,
                                         float* __restrict__ out) {
    if (blockIdx.x < K2_LINK) {
        // ---- link term (memory-latency bound; independent of gather) ----
        const int b = blockIdx.x;
        const int stride = K2_LINK * BT;
        float acc = 0.0f;
        for (int e = b * BT + threadIdx.x; e < NLINKS; e += stride) {
            const int i = li[e];
            const int j = lj[e];
            const float4 a0 = __ldg((const float4*)&zi[i * 8]);
            const float4 a1 = __ldg((const float4*)&zi[i * 8 + 4]);
            const float4 b0 = __ldg((const float4*)&zj[j * 8]);
            const float4 b1 = __ldg((const float4*)&zj[j * 8 + 4]);
            float d0 = a0.x - b0.x + EPSF, d1 = a0.y - b0.y + EPSF;
            float d2 = a0.z - b0.z + EPSF, d3 = a0.w - b0.w + EPSF;
            float d4 = a1.x - b1.x + EPSF, d5 = a1.y - b1.y + EPSF;
            float d6 = a1.z - b1.z + EPSF, d7 = a1.w - b1.w + EPSF;
            float s = d0 * d0;
            s = fmaf(d1, d1, s); s = fmaf(d2, d2, s); s = fmaf(d3, d3, s);
            s = fmaf(d4, d4, s); s = fmaf(d5, d5, s); s = fmaf(d6, d6, s);
            s = fmaf(d7, d7, s);
            float u = rsqrtf(s);
            acc += __ldg(&beta[i]) + __ldg(&gamma[j]) - s * u;
        }
        float tot = block_sum(acc);
        if (threadIdx.x == 0) g_part_links[b] = tot;
    } else {
        // ---- sampled block term (issue-bound; packed f32x2 math) ----
        const int ib = (blockIdx.x - K2_LINK) * IT;

        u64 A01[IT], A23[IT], A45[IT], A67[IT];
        float bL[IT];
        #pragma unroll
        for (int u = 0; u < IT; u++) {
            const ulonglong2 p0 = *(const ulonglong2*)&g_zi0[ib + u];
            const ulonglong2 p1 = *(const ulonglong2*)&g_zi1[ib + u];
            A01[u] = p0.x; A23[u] = p0.y; A45[u] = p1.x; A67[u] = p1.y;
            bL[u] = g_bL[ib + u];
        }

        float acc[IT];
        #pragma unroll
        for (int u = 0; u < IT; u++) acc[u] = 0.0f;

        const ulonglong2* __restrict__ ZJ0 = (const ulonglong2*)g_zj0;
        const ulonglong2* __restrict__ ZJ1 = (const ulonglong2*)g_zj1;

        for (int j = threadIdx.x; j < SJ; j += BT) {
            const ulonglong2 q0 = ZJ0[j];      // packed (-zj) halves
            const ulonglong2 q1 = ZJ1[j];
            const float gL = g_gL[j];
            #pragma unroll
            for (int u = 0; u < IT; u++) {
                u64 d01 = ADD2(A01[u], q0.x);
                u64 d23 = ADD2(A23[u], q0.y);
                u64 d45 = ADD2(A45[u], q1.x);
                u64 d67 = ADD2(A67[u], q1.y);
                u64 sp  = MUL2(d01, d01);
                sp = FMA2(d23, d23, sp);
                sp = FMA2(d45, d45, sp);
                sp = FMA2(d67, d67, sp);
                float s = LOHI_ADD(sp);
                float r = rsqrtf(s);                      // MUFU.RSQ
                float t = fmaf(s * r, -L2E, bL[u] + gL);  // log2-domain exponent
                float e;
                asm("ex2.approx.f32 %0, %1;" : "=f"(e) : "f"(t));  // MUFU.EX2
                acc[u] += e;
            }
        }
        float tot = block_sum(acc[0] + acc[1] + acc[2] + acc[3]);
        if (threadIdx.x == 0) g_part_block[blockIdx.x - K2_LINK] = tot;
    }

    // ---- last-arriving block performs the deterministic final reduction ----
    __shared__ int isLast;
    __threadfence();
    if (threadIdx.x == 0) isLast = (atomicAdd(&g_ticket, 1) == K2_TOTAL - 1);
    __syncthreads();
    if (!isLast) return;

    __shared__ double redB[BT], redL[BT];
    double sb = 0.0, sl = 0.0;
    for (int k = threadIdx.x; k < NBI; k += BT)     sb += (double)g_part_block[k];
    for (int k = threadIdx.x; k < K2_LINK; k += BT) sl += (double)g_part_links[k];
    redB[threadIdx.x] = sb;
    redL[threadIdx.x] = sl;
    __syncthreads();
    #pragma unroll
    for (int s2 = BT / 2; s2 > 0; s2 >>= 1) {
        if (threadIdx.x < s2) {
            redB[threadIdx.x] += redB[threadIdx.x + s2];
            redL[threadIdx.x] += redL[threadIdx.x + s2];
        }
        __syncthreads();
    }
    if (threadIdx.x == 0) out[0] = (float)(redL[0] - redB[0]);
}

extern "C" void kernel_launch(void* const* d_in, const int* in_sizes, int n_in,
                              void* d_out, int out_size) {
    const float* latent_zi = (const float*)d_in[0];
    const float* latent_zj = (const float*)d_in[1];
    const float* beta      = (const float*)d_in[2];
    const float* gamma     = (const float*)d_in[3];
    const int*   si        = (const int*)  d_in[4];
    const int*   sj        = (const int*)  d_in[5];
    const int*   li        = (const int*)  d_in[6];
    const int*   lj        = (const int*)  d_in[7];
    float* out = (float*)d_out;

    k1<<<GATHER_BLOCKS, BT>>>(latent_zi, latent_zj, beta, gamma, si, sj);
    k2<<<K2_TOTAL, BT>>>(latent_zi, latent_zj, beta, gamma, li, lj, out);
}